// round 14
// baseline (speedup 1.0000x reference)
#include <cuda_runtime.h>
#include <cuda_bf16.h>
#include <cuda_fp16.h>
#include <cstdint>
#include <math.h>

// ---------------------------------------------------------------------------
// Problem constants
// ---------------------------------------------------------------------------
#define S_LEN 2048
#define HDIM  2048
#define NH    32
#define NKV   8
#define HD    64
#define GROUPS 4
#define DFF   8192
#define NKB   256
#define KBLEN 257
#define KBPAD 320
#define EPSV  1e-5f
#define ESC   0.18033688011112042f   // 0.125 * log2(e)

// ---------------------------------------------------------------------------
// Scratch (device globals)
// ---------------------------------------------------------------------------
__device__ float g_H[S_LEN * HDIM];

__device__ __half g_Wqf [NH * HD * HDIM];
__device__ __half g_Wkf [NKV * HD * HDIM];
__device__ __half g_Wvf [NKV * HD * HDIM];
__device__ __half g_Wqnf[NH * HD * HDIM];
__device__ __half g_Wkkf[NKV * HD * HDIM];
__device__ __half g_Wkvf[NKV * HD * HDIM];
__device__ __half g_Wof [HDIM * NH * HD];
__device__ __half g_Wupf[DFF * HDIM];
__device__ __half g_Wdnf[HDIM * DFF];

__device__ __half g_X1f [S_LEN * HDIM];
__device__ __half g_X2f [S_LEN * HDIM];
__device__ __half g_KIKf[NKB * HDIM];
__device__ __half g_KIVf[NKB * HDIM];
__device__ __half g_Qf  [S_LEN * NH * HD];
__device__ __half g_QNf [S_LEN * NH * HD];
__device__ __half g_Kf  [S_LEN * NKV * HD];
__device__ __half g_Vf  [S_LEN * NKV * HD];
__device__ __half g_KTKf[NKB * NKV * HD];
__device__ __half g_KTVf[NKB * NKV * HD];
__device__ __half g_KBKf[NKV * KBPAD * HD];
__device__ __half g_KBVf[NKV * KBPAD * HD];
__device__ __half g_ATf [S_LEN * NH * HD];
__device__ __half g_Uf  [S_LEN * DFF];

// ---------------------------------------------------------------------------
// Helpers
// ---------------------------------------------------------------------------
__device__ __forceinline__ unsigned smem_u32(const void* p) {
    return (unsigned)__cvta_generic_to_shared(p);
}
__device__ __forceinline__ void ldsm_x4(unsigned addr, unsigned &r0, unsigned &r1,
                                        unsigned &r2, unsigned &r3) {
    asm volatile("ldmatrix.sync.aligned.m8n8.x4.shared.b16 {%0,%1,%2,%3}, [%4];"
                 : "=r"(r0), "=r"(r1), "=r"(r2), "=r"(r3) : "r"(addr));
}
__device__ __forceinline__ void ldsm_x4_t(unsigned addr, unsigned &r0, unsigned &r1,
                                          unsigned &r2, unsigned &r3) {
    asm volatile("ldmatrix.sync.aligned.m8n8.x4.trans.shared.b16 {%0,%1,%2,%3}, [%4];"
                 : "=r"(r0), "=r"(r1), "=r"(r2), "=r"(r3) : "r"(addr));
}
__device__ __forceinline__ void mma_f16(float* c, const unsigned* a, const unsigned* b) {
    asm volatile("mma.sync.aligned.m16n8k16.row.col.f32.f16.f16.f32 "
                 "{%0,%1,%2,%3}, {%4,%5,%6,%7}, {%8,%9}, {%0,%1,%2,%3};"
                 : "+f"(c[0]), "+f"(c[1]), "+f"(c[2]), "+f"(c[3])
                 : "r"(a[0]), "r"(a[1]), "r"(a[2]), "r"(a[3]),
                   "r"(b[0]), "r"(b[1]));
}
__device__ __forceinline__ void mma_f16acc(unsigned* c, const unsigned* a, const unsigned* b) {
    asm volatile("mma.sync.aligned.m16n8k16.row.col.f16.f16.f16.f16 "
                 "{%0,%1}, {%2,%3,%4,%5}, {%6,%7}, {%0,%1};"
                 : "+r"(c[0]), "+r"(c[1])
                 : "r"(a[0]), "r"(a[1]), "r"(a[2]), "r"(a[3]),
                   "r"(b[0]), "r"(b[1]));
}
__device__ __forceinline__ unsigned ex2_h2(unsigned x) {
    unsigned y;
    asm("ex2.approx.f16x2 %0, %1;" : "=r"(y) : "r"(x));
    return y;
}
__device__ __forceinline__ void cp16(unsigned dst, const void* src) {
    asm volatile("cp.async.cg.shared.global [%0], [%1], 16;" :: "r"(dst), "l"(src));
}
__device__ __forceinline__ uint2 cvt4(float4 v) {
    __half2 h01 = __floats2half2_rn(v.x, v.y);
    __half2 h23 = __floats2half2_rn(v.z, v.w);
    uint2 o;
    o.x = *(unsigned*)&h01; o.y = *(unsigned*)&h23;
    return o;
}

// ---------------------------------------------------------------------------
// Fused fp32->fp16 convert for all weights + KB inputs (one launch).
// ---------------------------------------------------------------------------
#define C1 1048576
#define C2 2097152
#define C3 2359296
#define C4 2621440
#define C5 2883584
#define C6 3145728
#define C7 4194304
#define C8 8388608
#define C9 12582912
#define C10 12713984
#define CTOT 12845056

__global__ __launch_bounds__(256) void cvt_all_kernel(
    const float4* __restrict__ q,   const float4* __restrict__ qn,
    const float4* __restrict__ k,   const float4* __restrict__ v,
    const float4* __restrict__ kbk, const float4* __restrict__ kbv,
    const float4* __restrict__ o,   const float4* __restrict__ up,
    const float4* __restrict__ dn,  const float4* __restrict__ kbi,
    const float4* __restrict__ kbvv,
    uint2* __restrict__ dq,   uint2* __restrict__ dqn,
    uint2* __restrict__ dk,   uint2* __restrict__ dv,
    uint2* __restrict__ dkbk, uint2* __restrict__ dkbv,
    uint2* __restrict__ dox,  uint2* __restrict__ dup,
    uint2* __restrict__ ddn,  uint2* __restrict__ dkbi,
    uint2* __restrict__ dkbvv)
{
    int base = blockIdx.x * 1024 + threadIdx.x;
    #pragma unroll
    for (int u = 0; u < 4; u++) {
        int i = base + u * 256;
        if (i >= CTOT) return;
        const float4* s; uint2* d; int off;
        if      (i < C1)  { s = q;    d = dq;    off = i;       }
        else if (i < C2)  { s = qn;   d = dqn;   off = i - C1;  }
        else if (i < C3)  { s = k;    d = dk;    off = i - C2;  }
        else if (i < C4)  { s = v;    d = dv;    off = i - C3;  }
        else if (i < C5)  { s = kbk;  d = dkbk;  off = i - C4;  }
        else if (i < C6)  { s = kbv;  d = dkbv;  off = i - C5;  }
        else if (i < C7)  { s = o;    d = dox;   off = i - C6;  }
        else if (i < C8)  { s = up;   d = dup;   off = i - C7;  }
        else if (i < C9)  { s = dn;   d = ddn;   off = i - C8;  }
        else if (i < C10) { s = kbi;  d = dkbi;  off = i - C9;  }
        else              { s = kbvv; d = dkbvv; off = i - C10; }
        d[off] = cvt4(s[off]);
    }
}

// ---------------------------------------------------------------------------
// RMSNorm, single fp16 out
// ---------------------------------------------------------------------------
__global__ __launch_bounds__(256) void rmsnorm_h_kernel(
    const float* __restrict__ x, const float* __restrict__ w,
    __half* __restrict__ y)
{
    __shared__ float red[8];
    int row = blockIdx.x;
    const float4* xr = (const float4*)(x + (size_t)row * HDIM);
    int t = threadIdx.x;
    float4 v0 = xr[t];
    float4 v1 = xr[t + 256];
    float ss = v0.x*v0.x + v0.y*v0.y + v0.z*v0.z + v0.w*v0.w
             + v1.x*v1.x + v1.y*v1.y + v1.z*v1.z + v1.w*v1.w;
    #pragma unroll
    for (int o = 16; o; o >>= 1) ss += __shfl_xor_sync(0xffffffffu, ss, o);
    if ((t & 31) == 0) red[t >> 5] = ss;
    __syncthreads();
    if (t < 32) {
        float s = (t < 8) ? red[t] : 0.f;
        #pragma unroll
        for (int o = 4; o; o >>= 1) s += __shfl_xor_sync(0xffffffffu, s, o);
        if (t == 0) red[0] = rsqrtf(s * (1.0f / HDIM) + EPSV);
    }
    __syncthreads();
    float r = red[0];
    const float4* wv = (const float4*)w;
    float4 w0 = wv[t], w1 = wv[t + 256];
    __half2 p0 = __floats2half2_rn(v0.x * r * w0.x, v0.y * r * w0.y);
    __half2 p1 = __floats2half2_rn(v0.z * r * w0.z, v0.w * r * w0.w);
    __half2 p2 = __floats2half2_rn(v1.x * r * w1.x, v1.y * r * w1.y);
    __half2 p3 = __floats2half2_rn(v1.z * r * w1.z, v1.w * r * w1.w);
    size_t base = (size_t)row * HDIM + 4 * t;
    uint2 a, b;
    a.x = *(unsigned*)&p0; a.y = *(unsigned*)&p1;
    b.x = *(unsigned*)&p2; b.y = *(unsigned*)&p3;
    *(uint2*)(y + base)        = a;
    *(uint2*)(y + base + 1024) = b;
}

// ---------------------------------------------------------------------------
// Single-fp16 1-MMA GEMM, BK=64, 3-stage cp.async pipeline, 1 barrier/K-iter.
// C = op(A @ B^T). 2 CTAs/SM. blockIdx.z selects alternate operand set.
// OP: 1 = +D (f32 out), 2 = relu^2 (fp16 out), 3 = *esc (fp16 out)
// ---------------------------------------------------------------------------
#define KST 72
#define MAT_B2 (128 * KST * 2)       // 18432 B per 128x64 fp16 matrix
#define SSTAGE_B (2 * MAT_B2)        // A + B per stage = 36864 B
#define SSM_TOT (3 * SSTAGE_B)       // 110592 B

template<int OP>
__global__ __launch_bounds__(256, 2) void gemm_s(
    const __half* __restrict__ A,  const __half* __restrict__ B,
    const __half* __restrict__ A1, const __half* __restrict__ B1,
    float* __restrict__ Cf, const float* __restrict__ D,
    __half* __restrict__ Ch, __half* __restrict__ Ch1,
    int M, int N, int K, float esc)
{
    extern __shared__ char sm[];
    if (blockIdx.z) { A = A1; B = B1; Ch = Ch1; }

    int tid = threadIdx.x;
    int bm = blockIdx.y * 128;
    int bn = blockIdx.x * 128;

    int lrow = tid >> 1;
    int lcol = (tid & 1) * 32;
    const __half* gA = A + (size_t)(bm + lrow) * K + lcol;
    const __half* gB = B + (size_t)(bn + lrow) * K + lcol;
    unsigned sBase = smem_u32(sm);
    unsigned sOff = (unsigned)(lrow * KST + lcol) * 2u;

    auto issue = [&](int stage, int k0) {
        unsigned d = sBase + stage * SSTAGE_B + sOff;
        #pragma unroll
        for (int u = 0; u < 4; u++) {
            cp16(d + u * 16,          gA + k0 + u * 8);
            cp16(d + MAT_B2 + u * 16, gB + k0 + u * 8);
        }
        asm volatile("cp.async.commit_group;" ::: "memory");
    };

    int wid  = tid >> 5;
    int lane = tid & 31;
    int wm = (wid >> 1) * 32;
    int wn = (wid & 1) * 64;

    float acc[2][8][4];
    #pragma unroll
    for (int i = 0; i < 2; i++)
        #pragma unroll
        for (int j = 0; j < 8; j++)
            #pragma unroll
            for (int c = 0; c < 4; c++) acc[i][j][c] = 0.f;

    int aTerm = (wm + (lane & 15)) * KST + (lane >> 4) * 8;
    int bTerm = (wn + (lane & 15)) * KST + (lane >> 4) * 8;

    int kIters = K / 64;
    issue(0, 0);
    if (kIters > 1) issue(1, 64);

    for (int it = 0; it < kIters; it++) {
        if (it + 1 < kIters) asm volatile("cp.async.wait_group 1;" ::: "memory");
        else                 asm volatile("cp.async.wait_group 0;" ::: "memory");
        __syncthreads();
        if (it + 2 < kIters) issue((it + 2) % 3, (it + 2) * 64);

        unsigned base = sBase + (unsigned)(it % 3) * SSTAGE_B;
        #pragma unroll
        for (int ks = 0; ks < 4; ks++) {
            int ko = ks * 16;
            unsigned a[2][4];
            #pragma unroll
            for (int mt = 0; mt < 2; mt++) {
                unsigned off = (unsigned)(aTerm + mt * 16 * KST + ko) * 2u;
                ldsm_x4(base + off, a[mt][0], a[mt][1], a[mt][2], a[mt][3]);
            }
            #pragma unroll
            for (int nt2 = 0; nt2 < 4; nt2++) {
                unsigned off = (unsigned)(bTerm + nt2 * 16 * KST + ko) * 2u;
                unsigned r0, r1, r2, r3;
                ldsm_x4(base + MAT_B2 + off, r0, r1, r2, r3);
                unsigned b0[2] = {r0, r2}, b1[2] = {r1, r3};
                #pragma unroll
                for (int mt = 0; mt < 2; mt++) {
                    mma_f16(acc[mt][2*nt2],   a[mt], b0);
                    mma_f16(acc[mt][2*nt2+1], a[mt], b1);
                }
            }
        }
    }

    int gr = bm + wm + (lane >> 2);
    int gc = bn + wn + (lane & 3) * 2;
    #pragma unroll
    for (int mt = 0; mt < 2; mt++) {
        #pragma unroll
        for (int nt = 0; nt < 8; nt++) {
            int col = gc + nt * 8;
            #pragma unroll
            for (int half = 0; half < 2; half++) {
                int row = gr + mt * 16 + half * 8;
                size_t idx = (size_t)row * N + col;
                float rx = acc[mt][nt][half * 2 + 0];
                float ry = acc[mt][nt][half * 2 + 1];
                if (OP == 1) {
                    float2 d2 = *(const float2*)(D + idx);
                    float2 r; r.x = rx + d2.x; r.y = ry + d2.y;
                    *(float2*)(Cf + idx) = r;
                } else if (OP == 2) {
                    rx = fmaxf(rx, 0.f); rx *= rx;
                    ry = fmaxf(ry, 0.f); ry *= ry;
                    *(__half2*)(Ch + idx) = __floats2half2_rn(rx, ry);
                } else {
                    *(__half2*)(Ch + idx) = __floats2half2_rn(rx * esc, ry * esc);
                }
            }
        }
    }
}

// ---------------------------------------------------------------------------
// RoPE in-place on fp16 Q [S,32,64] (ESC-scaled) and K [S,8,64]
// ---------------------------------------------------------------------------
__global__ __launch_bounds__(256) void rope_inplace_kernel(
    __half* __restrict__ Q, __half* __restrict__ K, const int* __restrict__ pos)
{
    int idx = blockIdx.x * blockDim.x + threadIdx.x;
    if (idx >= S_LEN * 40 * 32) return;
    int d  = idx & 31;
    int hh = (idx >> 5) % 40;
    int s  = idx / (40 * 32);

    float inv = exp2f((float)d * (-13.287712379549449f / 32.0f));
    float ang = (float)pos[s] * inv;
    float sn, cs;
    sincosf(ang, &sn, &cs);

    __half* ptr = (hh < 32) ? (Q + (size_t)s * (NH * HD) + hh * HD)
                            : (K + (size_t)s * (NKV * HD) + (hh - 32) * HD);
    float x1 = __half2float(ptr[d]);
    float x2 = __half2float(ptr[d + 32]);
    ptr[d]      = __float2half_rn(x1 * cs - x2 * sn);
    ptr[d + 32] = __float2half_rn(x2 * cs + x1 * sn);
}

// ---------------------------------------------------------------------------
// Assemble KB K/V (fp16 in, fp16 out), padded [8,320,64]
// ---------------------------------------------------------------------------
__global__ __launch_bounds__(256) void kb_assemble_h_kernel(
    const __half* __restrict__ ktmp, const __half* __restrict__ vtmp,
    const float* __restrict__ sink_k, const float* __restrict__ sink_v,
    __half* __restrict__ kbk, __half* __restrict__ kbv)
{
    int idx = blockIdx.x * blockDim.x + threadIdx.x;
    if (idx >= NKV * KBPAD * HD) return;
    int d = idx % HD;
    int n = (idx / HD) % KBPAD;
    int g = idx / (HD * KBPAD);
    __half kv = __float2half_rn(0.f), vv = kv;
    if (n == 0) {
        kv = __float2half_rn(sink_k[g * HD + d]);
        vv = __float2half_rn(sink_v[g * HD + d]);
    } else if (n < KBLEN) {
        size_t src = (size_t)(n - 1) * (NKV * HD) + g * HD + d;
        kv = ktmp[src];
        vv = vtmp[src];
    }
    kbk[idx] = kv;
    kbv[idx] = vv;
}

// ---------------------------------------------------------------------------
// Tensor-core rectangular flash attention, all-fp16 operands, f16-acc QK,
// no online max (scores bounded), 2 CTAs/SM.
// ---------------------------------------------------------------------------
#define ATT_ST 72
#define ATT_MATB (64 * ATT_ST * 2)
#define ATT_STGB (2 * ATT_MATB)
#define ATT_QB   (128 * ATT_ST * 2)
#define ATT_SMEM (2 * ATT_STGB + ATT_QB)

__global__ __launch_bounds__(256, 2) void attn_tc_kernel(
    const __half* __restrict__ Qf,  const __half* __restrict__ QNf,
    const __half* __restrict__ Kf,  const __half* __restrict__ Vf,
    const __half* __restrict__ KBKf, const __half* __restrict__ KBVf,
    __half* __restrict__ Of)
{
    extern __shared__ __align__(128) char smraw[];
    unsigned sb = smem_u32(smraw);
    unsigned q_s = sb;
    unsigned stg = sb + ATT_QB;

    int tid = threadIdx.x, wid = tid >> 5, lane = tid & 31;
    int h = blockIdx.y, g = h >> 2;
    int q0 = blockIdx.x * 128;
    int wq = wid * 16;

    float oacc[8][4];
    #pragma unroll
    for (int nt = 0; nt < 8; nt++)
        #pragma unroll
        for (int e = 0; e < 4; e++) oacc[nt][e] = 0.f;
    float lacc[4] = {0.f, 0.f, 0.f, 0.f};
    const unsigned ONES2[2] = {0x3C003C00u, 0x3C003C00u};

    const int aTerm = ((wq + (lane & 15)) * ATT_ST + (lane >> 4) * 8) * 2;
    const int bTerm = (((lane & 15)) * ATT_ST + (lane >> 4) * 8) * 2;

    int r0w = q0 + wq + (lane >> 2);

    for (int phase = 0; phase < 2; phase++) {
        const __half* qsrc = phase ? Qf : QNf;

        __syncthreads();
        #pragma unroll
        for (int u = 0; u < 4; u++) {
            int c = u * 256 + tid;
            int row = c >> 3, cu = c & 7;
            size_t gsrc = (size_t)(q0 + row) * (NH * HD) + h * HD + cu * 8;
            cp16(q_s + (unsigned)(row * ATT_ST * 2 + cu * 16), qsrc + gsrc);
        }
        asm volatile("cp.async.commit_group;" ::: "memory");
        asm volatile("cp.async.wait_group 0;" ::: "memory");
        __syncthreads();

        unsigned qa[4][4];
        #pragma unroll
        for (int ks = 0; ks < 4; ks++)
            ldsm_x4(q_s + aTerm + ks * 32, qa[ks][0], qa[ks][1], qa[ks][2], qa[ks][3]);

        int nb = phase ? ((q0 + 128) >> 6) : (KBPAD >> 6);

        auto kload = [&](int j) {
            unsigned base = stg + (unsigned)(j & 1) * ATT_STGB;
            #pragma unroll
            for (int mt = 0; mt < 2; mt++) {
                const __half* src = phase ? (mt ? Vf : Kf) : (mt ? KBVf : KBKf);
                #pragma unroll
                for (int u = 0; u < 2; u++) {
                    int c = u * 256 + tid;
                    int row = c >> 3, cu = c & 7;
                    size_t gsrc = phase
                        ? ((size_t)(j * 64 + row) * (NKV * HD) + g * HD + cu * 8)
                        : ((size_t)(g * KBPAD + j * 64 + row) * HD + cu * 8);
                    cp16(base + mt * ATT_MATB + (unsigned)(row * ATT_ST * 2 + cu * 16),
                         src + gsrc);
                }
            }
            asm volatile("cp.async.commit_group;" ::: "memory");
        };

        kload(0);

        for (int j = 0; j < nb; j++) {
            if (j + 1 < nb) {
                kload(j + 1);
                asm volatile("cp.async.wait_group 1;" ::: "memory");
            } else {
                asm volatile("cp.async.wait_group 0;" ::: "memory");
            }
            __syncthreads();
            unsigned base = stg + (unsigned)(j & 1) * ATT_STGB;

            int wrow = q0 + wq;
            bool fullMask = phase && (64 * j > wrow + 15);
            if (!fullMask) {
                unsigned sc[8][2];
                #pragma unroll
                for (int nt = 0; nt < 8; nt++) { sc[nt][0] = 0u; sc[nt][1] = 0u; }

                #pragma unroll
                for (int ks = 0; ks < 4; ks++) {
                    #pragma unroll
                    for (int nt2 = 0; nt2 < 4; nt2++) {
                        unsigned off = (unsigned)(bTerm + nt2 * 16 * ATT_ST * 2 + ks * 32);
                        unsigned r0, r1, r2, r3;
                        ldsm_x4(base + off, r0, r1, r2, r3);
                        unsigned bh0[2] = {r0, r2}, bh1[2] = {r1, r3};
                        mma_f16acc(sc[2*nt2],   qa[ks], bh0);
                        mma_f16acc(sc[2*nt2+1], qa[ks], bh1);
                    }
                }

                bool needMask = phase ? (64 * j + 63 > wrow) : (j == nb - 1);
                if (needMask) {
                    int cb = j * 64 + (lane & 3) * 2;
                    #pragma unroll
                    for (int nt = 0; nt < 8; nt++) {
                        int c0 = cb + nt * 8, c1 = c0 + 1;
                        #pragma unroll
                        for (int e = 0; e < 2; e++) {
                            int row = r0w + e * 8;
                            bool m0 = phase ? (c0 > row) : (c0 >= KBLEN);
                            bool m1 = phase ? (c1 > row) : (c1 >= KBLEN);
                            if (m0 | m1) {
                                __half2 add = __floats2half2_rn(m0 ? -1e4f : 0.f,
                                                                m1 ? -1e4f : 0.f);
                                __half2 v = *(__half2*)&sc[nt][e];
                                v = __hadd2(v, add);
                                sc[nt][e] = *(unsigned*)&v;
                            }
                        }
                    }
                }

                unsigned ph[4][4];
                #pragma unroll
                for (int kk = 0; kk < 4; kk++) {
                    ph[kk][0] = ex2_h2(sc[2*kk][0]);
                    ph[kk][1] = ex2_h2(sc[2*kk][1]);
                    ph[kk][2] = ex2_h2(sc[2*kk+1][0]);
                    ph[kk][3] = ex2_h2(sc[2*kk+1][1]);
                }

                #pragma unroll
                for (int kk = 0; kk < 4; kk++)
                    mma_f16(lacc, ph[kk], ONES2);

                #pragma unroll
                for (int kk = 0; kk < 4; kk++) {
                    #pragma unroll
                    for (int nt2 = 0; nt2 < 4; nt2++) {
                        unsigned voff = (unsigned)(((kk * 16 + (lane & 15)) * ATT_ST
                                        + (lane >> 4) * 8 + nt2 * 16) * 2);
                        unsigned t0, t1, t2, t3;
                        ldsm_x4_t(base + ATT_MATB + voff, t0, t1, t2, t3);
                        unsigned vh0[2] = {t0, t1}, vh1[2] = {t2, t3};
                        mma_f16(oacc[2*nt2],   ph[kk], vh0);
                        mma_f16(oacc[2*nt2+1], ph[kk], vh1);
                    }
                }
            }
            __syncthreads();
        }
    }

    float inv0 = 1.0f / lacc[0], inv1 = 1.0f / lacc[2];

    #pragma unroll
    for (int nt = 0; nt < 8; nt++) {
        int col = h * HD + nt * 8 + (lane & 3) * 2;
        {
            __half2 hh = __floats2half2_rn(oacc[nt][0] * inv0, oacc[nt][1] * inv0);
            *(__half2*)(Of + (size_t)r0w * (NH * HD) + col) = hh;
        }
        {
            __half2 hh = __floats2half2_rn(oacc[nt][2] * inv1, oacc[nt][3] * inv1);
            *(__half2*)(Of + (size_t)(r0w + 8) * (NH * HD) + col) = hh;
        }
    }
}

// ---------------------------------------------------------------------------
// kernel_launch
// ---------------------------------------------------------------------------
extern "C" void kernel_launch(void* const* d_in, const int* in_sizes, int n_in,
                              void* d_out, int out_size)
{
    const float* hid     = (const float*)d_in[0];
    const float* kb_keys = (const float*)d_in[1];
    const float* kb_vals = (const float*)d_in[2];
    const float* q_w     = (const float*)d_in[3];
    const float* k_w     = (const float*)d_in[4];
    const float* v_w     = (const float*)d_in[5];
    const float* o_w     = (const float*)d_in[6];
    const float* qnew_w  = (const float*)d_in[7];
    const float* kbk_w   = (const float*)d_in[8];
    const float* kbv_w   = (const float*)d_in[9];
    const float* sink_k  = (const float*)d_in[10];
    const float* sink_v  = (const float*)d_in[11];
    const float* ln1_w   = (const float*)d_in[12];
    const float* ln2_w   = (const float*)d_in[13];
    const float* up_w    = (const float*)d_in[14];
    const float* down_w  = (const float*)d_in[15];
    const int*   pos     = (const int*)d_in[16];
    float* out = (float*)d_out;

    float* H;
    cudaGetSymbolAddress((void**)&H, g_H);

    __half *Wqf,*Wkf,*Wvf,*Wqnf,*Wkkf,*Wkvf,*Wof,*Wupf,*Wdnf;
    __half *X1f,*X2f,*KIKf,*KIVf,*Qf,*QNf,*Kf,*Vf,*KTKf,*KTVf,*KBKf,*KBVf,*ATf,*Uf;
    cudaGetSymbolAddress((void**)&Wqf,  g_Wqf);
    cudaGetSymbolAddress((void**)&Wkf,  g_Wkf);
    cudaGetSymbolAddress((void**)&Wvf,  g_Wvf);
    cudaGetSymbolAddress((void**)&Wqnf, g_Wqnf);
    cudaGetSymbolAddress((void**)&Wkkf, g_Wkkf);
    cudaGetSymbolAddress((void**)&Wkvf, g_Wkvf);
    cudaGetSymbolAddress((void**)&Wof,  g_Wof);
    cudaGetSymbolAddress((void**)&Wupf, g_Wupf);
    cudaGetSymbolAddress((void**)&Wdnf, g_Wdnf);
    cudaGetSymbolAddress((void**)&X1f, g_X1f);  cudaGetSymbolAddress((void**)&X2f, g_X2f);
    cudaGetSymbolAddress((void**)&KIKf,g_KIKf); cudaGetSymbolAddress((void**)&KIVf,g_KIVf);
    cudaGetSymbolAddress((void**)&Qf,  g_Qf);   cudaGetSymbolAddress((void**)&QNf, g_QNf);
    cudaGetSymbolAddress((void**)&Kf,  g_Kf);   cudaGetSymbolAddress((void**)&Vf,  g_Vf);
    cudaGetSymbolAddress((void**)&KTKf,g_KTKf); cudaGetSymbolAddress((void**)&KTVf,g_KTVf);
    cudaGetSymbolAddress((void**)&KBKf,g_KBKf); cudaGetSymbolAddress((void**)&KBVf,g_KBVf);
    cudaGetSymbolAddress((void**)&ATf, g_ATf);  cudaGetSymbolAddress((void**)&Uf,  g_Uf);

    cudaFuncSetAttribute(gemm_s<1>, cudaFuncAttributeMaxDynamicSharedMemorySize, SSM_TOT);
    cudaFuncSetAttribute(gemm_s<2>, cudaFuncAttributeMaxDynamicSharedMemorySize, SSM_TOT);
    cudaFuncSetAttribute(gemm_s<3>, cudaFuncAttributeMaxDynamicSharedMemorySize, SSM_TOT);
    cudaFuncSetAttribute(attn_tc_kernel, cudaFuncAttributeMaxDynamicSharedMemorySize, ATT_SMEM);

    dim3 blk(256);
    size_t ssm = SSM_TOT;

    // 1: all weight + kb-input converts in one launch
    cvt_all_kernel<<<(CTOT + 1023) / 1024, blk>>>(
        (const float4*)q_w, (const float4*)qnew_w, (const float4*)k_w,
        (const float4*)v_w, (const float4*)kbk_w, (const float4*)kbv_w,
        (const float4*)o_w, (const float4*)up_w, (const float4*)down_w,
        (const float4*)kb_keys, (const float4*)kb_vals,
        (uint2*)Wqf, (uint2*)Wqnf, (uint2*)Wkf, (uint2*)Wvf,
        (uint2*)Wkkf, (uint2*)Wkvf, (uint2*)Wof, (uint2*)Wupf,
        (uint2*)Wdnf, (uint2*)KIKf, (uint2*)KIVf);

    // 2: ln1
    rmsnorm_h_kernel<<<S_LEN, blk>>>(hid, ln1_w, X1f);

    // 3: q + qnew projections (ESC folded)
    gemm_s<3><<<dim3(16, 16, 2), blk, ssm>>>(X1f, Wqf, X1f, Wqnf,
                                             nullptr, nullptr, Qf, QNf,
                                             S_LEN, NH * HD, HDIM, ESC);
    // 4: k + v projections
    gemm_s<3><<<dim3(4, 16, 2), blk, ssm>>>(X1f, Wkf, X1f, Wvf,
                                            nullptr, nullptr, Kf, Vf,
                                            S_LEN, NKV * HD, HDIM, 1.f);
    // 5: kb projections
    gemm_s<3><<<dim3(4, 2, 2), blk, ssm>>>(KIKf, Wkkf, KIVf, Wkvf,
                                           nullptr, nullptr, KTKf, KTVf,
                                           NKB, NKV * HD, HDIM, 1.f);

    // 6: rope in place
    rope_inplace_kernel<<<(S_LEN * 40 * 32) / 256, blk>>>(Qf, Kf, pos);

    // 7: kb assemble
    kb_assemble_h_kernel<<<(NKV * KBPAD * HD + 255) / 256, blk>>>(
        KTKf, KTVf, sink_k, sink_v, KBKf, KBVf);

    // 8: attention
    attn_tc_kernel<<<dim3(S_LEN / 128, NH), blk, ATT_SMEM>>>(
        Qf, QNf, Kf, Vf, KBKf, KBVf, ATf);

    // 9: o-proj + residual -> H (f32)
    gemm_s<1><<<dim3(16, 16, 1), blk, ssm>>>(ATf, Wof, ATf, Wof,
                                             H, hid, nullptr, nullptr,
                                             S_LEN, HDIM, NH * HD, 1.f);

    // 10: ln2
    rmsnorm_h_kernel<<<S_LEN, blk>>>(H, ln2_w, X2f);

    // 11: up proj + relu^2
    gemm_s<2><<<dim3(64, 16, 1), blk, ssm>>>(X2f, Wupf, X2f, Wupf,
                                             nullptr, nullptr, Uf, Uf,
                                             S_LEN, DFF, HDIM, 1.f);

    // 12: down proj + residual -> out
    gemm_s<1><<<dim3(16, 16, 1), blk, ssm>>>(Uf, Wdnf, Uf, Wdnf,
                                             out, H, nullptr, nullptr,
                                             S_LEN, HDIM, DFF, 1.f);
}

// round 15
// speedup vs baseline: 1.1410x; 1.1410x over previous
#include <cuda_runtime.h>
#include <cuda_bf16.h>
#include <cuda_fp16.h>
#include <cstdint>
#include <math.h>

// ---------------------------------------------------------------------------
// Problem constants
// ---------------------------------------------------------------------------
#define S_LEN 2048
#define HDIM  2048
#define NH    32
#define NKV   8
#define HD    64
#define GROUPS 4
#define DFF   8192
#define NKB   256
#define KBLEN 257
#define KBPAD 320
#define EPSV  1e-5f
#define ESC   0.18033688011112042f   // 0.125 * log2(e)

// ---------------------------------------------------------------------------
// Scratch (device globals)
// ---------------------------------------------------------------------------
__device__ float g_H[S_LEN * HDIM];

__device__ __half g_Wqf [NH * HD * HDIM];
__device__ __half g_Wkf [NKV * HD * HDIM];
__device__ __half g_Wvf [NKV * HD * HDIM];
__device__ __half g_Wqnf[NH * HD * HDIM];
__device__ __half g_Wkkf[NKV * HD * HDIM];
__device__ __half g_Wkvf[NKV * HD * HDIM];
__device__ __half g_Wof [HDIM * NH * HD];
__device__ __half g_Wupf[DFF * HDIM];
__device__ __half g_Wdnf[HDIM * DFF];

__device__ __half g_X1f [S_LEN * HDIM];
__device__ __half g_X2f [S_LEN * HDIM];
__device__ __half g_KIKf[NKB * HDIM];
__device__ __half g_KIVf[NKB * HDIM];
__device__ __half g_Qf  [S_LEN * NH * HD];
__device__ __half g_QNf [S_LEN * NH * HD];
__device__ __half g_Kf  [S_LEN * NKV * HD];
__device__ __half g_Vf  [S_LEN * NKV * HD];
__device__ __half g_KTKf[NKB * NKV * HD];
__device__ __half g_KTVf[NKB * NKV * HD];
__device__ __half g_KBKf[NKV * KBPAD * HD];
__device__ __half g_KBVf[NKV * KBPAD * HD];
__device__ __half g_ATf [S_LEN * NH * HD];
__device__ __half g_Uf  [S_LEN * DFF];

// ---------------------------------------------------------------------------
// Helpers
// ---------------------------------------------------------------------------
__device__ __forceinline__ unsigned smem_u32(const void* p) {
    return (unsigned)__cvta_generic_to_shared(p);
}
__device__ __forceinline__ void ldsm_x4(unsigned addr, unsigned &r0, unsigned &r1,
                                        unsigned &r2, unsigned &r3) {
    asm volatile("ldmatrix.sync.aligned.m8n8.x4.shared.b16 {%0,%1,%2,%3}, [%4];"
                 : "=r"(r0), "=r"(r1), "=r"(r2), "=r"(r3) : "r"(addr));
}
__device__ __forceinline__ void ldsm_x4_t(unsigned addr, unsigned &r0, unsigned &r1,
                                          unsigned &r2, unsigned &r3) {
    asm volatile("ldmatrix.sync.aligned.m8n8.x4.trans.shared.b16 {%0,%1,%2,%3}, [%4];"
                 : "=r"(r0), "=r"(r1), "=r"(r2), "=r"(r3) : "r"(addr));
}
__device__ __forceinline__ void mma_f16(float* c, const unsigned* a, const unsigned* b) {
    asm volatile("mma.sync.aligned.m16n8k16.row.col.f32.f16.f16.f32 "
                 "{%0,%1,%2,%3}, {%4,%5,%6,%7}, {%8,%9}, {%0,%1,%2,%3};"
                 : "+f"(c[0]), "+f"(c[1]), "+f"(c[2]), "+f"(c[3])
                 : "r"(a[0]), "r"(a[1]), "r"(a[2]), "r"(a[3]),
                   "r"(b[0]), "r"(b[1]));
}
__device__ __forceinline__ void mma_f16acc(unsigned* c, const unsigned* a, const unsigned* b) {
    asm volatile("mma.sync.aligned.m16n8k16.row.col.f16.f16.f16.f16 "
                 "{%0,%1}, {%2,%3,%4,%5}, {%6,%7}, {%0,%1};"
                 : "+r"(c[0]), "+r"(c[1])
                 : "r"(a[0]), "r"(a[1]), "r"(a[2]), "r"(a[3]),
                   "r"(b[0]), "r"(b[1]));
}
__device__ __forceinline__ unsigned ex2_h2(unsigned x) {
    unsigned y;
    asm("ex2.approx.f16x2 %0, %1;" : "=r"(y) : "r"(x));
    return y;
}
__device__ __forceinline__ void cp16(unsigned dst, const void* src) {
    asm volatile("cp.async.cg.shared.global [%0], [%1], 16;" :: "r"(dst), "l"(src));
}
__device__ __forceinline__ uint2 cvt4(float4 v) {
    __half2 h01 = __floats2half2_rn(v.x, v.y);
    __half2 h23 = __floats2half2_rn(v.z, v.w);
    uint2 o;
    o.x = *(unsigned*)&h01; o.y = *(unsigned*)&h23;
    return o;
}

// ---------------------------------------------------------------------------
// Fused fp32->fp16 convert for all weights + KB inputs (one launch).
// ---------------------------------------------------------------------------
#define C1 1048576
#define C2 2097152
#define C3 2359296
#define C4 2621440
#define C5 2883584
#define C6 3145728
#define C7 4194304
#define C8 8388608
#define C9 12582912
#define C10 12713984
#define CTOT 12845056

__global__ __launch_bounds__(256) void cvt_all_kernel(
    const float4* __restrict__ q,   const float4* __restrict__ qn,
    const float4* __restrict__ k,   const float4* __restrict__ v,
    const float4* __restrict__ kbk, const float4* __restrict__ kbv,
    const float4* __restrict__ o,   const float4* __restrict__ up,
    const float4* __restrict__ dn,  const float4* __restrict__ kbi,
    const float4* __restrict__ kbvv,
    uint2* __restrict__ dq,   uint2* __restrict__ dqn,
    uint2* __restrict__ dk,   uint2* __restrict__ dv,
    uint2* __restrict__ dkbk, uint2* __restrict__ dkbv,
    uint2* __restrict__ dox,  uint2* __restrict__ dup,
    uint2* __restrict__ ddn,  uint2* __restrict__ dkbi,
    uint2* __restrict__ dkbvv)
{
    int base = blockIdx.x * 1024 + threadIdx.x;
    #pragma unroll
    for (int u = 0; u < 4; u++) {
        int i = base + u * 256;
        if (i >= CTOT) return;
        const float4* s; uint2* d; int off;
        if      (i < C1)  { s = q;    d = dq;    off = i;       }
        else if (i < C2)  { s = qn;   d = dqn;   off = i - C1;  }
        else if (i < C3)  { s = k;    d = dk;    off = i - C2;  }
        else if (i < C4)  { s = v;    d = dv;    off = i - C3;  }
        else if (i < C5)  { s = kbk;  d = dkbk;  off = i - C4;  }
        else if (i < C6)  { s = kbv;  d = dkbv;  off = i - C5;  }
        else if (i < C7)  { s = o;    d = dox;   off = i - C6;  }
        else if (i < C8)  { s = up;   d = dup;   off = i - C7;  }
        else if (i < C9)  { s = dn;   d = ddn;   off = i - C8;  }
        else if (i < C10) { s = kbi;  d = dkbi;  off = i - C9;  }
        else              { s = kbvv; d = dkbvv; off = i - C10; }
        d[off] = cvt4(s[off]);
    }
}

// ---------------------------------------------------------------------------
// RMSNorm, single fp16 out
// ---------------------------------------------------------------------------
__global__ __launch_bounds__(256) void rmsnorm_h_kernel(
    const float* __restrict__ x, const float* __restrict__ w,
    __half* __restrict__ y)
{
    __shared__ float red[8];
    int row = blockIdx.x;
    const float4* xr = (const float4*)(x + (size_t)row * HDIM);
    int t = threadIdx.x;
    float4 v0 = xr[t];
    float4 v1 = xr[t + 256];
    float ss = v0.x*v0.x + v0.y*v0.y + v0.z*v0.z + v0.w*v0.w
             + v1.x*v1.x + v1.y*v1.y + v1.z*v1.z + v1.w*v1.w;
    #pragma unroll
    for (int o = 16; o; o >>= 1) ss += __shfl_xor_sync(0xffffffffu, ss, o);
    if ((t & 31) == 0) red[t >> 5] = ss;
    __syncthreads();
    if (t < 32) {
        float s = (t < 8) ? red[t] : 0.f;
        #pragma unroll
        for (int o = 4; o; o >>= 1) s += __shfl_xor_sync(0xffffffffu, s, o);
        if (t == 0) red[0] = rsqrtf(s * (1.0f / HDIM) + EPSV);
    }
    __syncthreads();
    float r = red[0];
    const float4* wv = (const float4*)w;
    float4 w0 = wv[t], w1 = wv[t + 256];
    __half2 p0 = __floats2half2_rn(v0.x * r * w0.x, v0.y * r * w0.y);
    __half2 p1 = __floats2half2_rn(v0.z * r * w0.z, v0.w * r * w0.w);
    __half2 p2 = __floats2half2_rn(v1.x * r * w1.x, v1.y * r * w1.y);
    __half2 p3 = __floats2half2_rn(v1.z * r * w1.z, v1.w * r * w1.w);
    size_t base = (size_t)row * HDIM + 4 * t;
    uint2 a, b;
    a.x = *(unsigned*)&p0; a.y = *(unsigned*)&p1;
    b.x = *(unsigned*)&p2; b.y = *(unsigned*)&p3;
    *(uint2*)(y + base)        = a;
    *(uint2*)(y + base + 1024) = b;
}

// ---------------------------------------------------------------------------
// GEMM core (BK=32, 3-stage pipeline, 1 barrier per K-iter) — round-13 proven.
// ---------------------------------------------------------------------------
#define TST 40
#define TILE_B 10240
#define SSTAGE_B 20480
#define SSM_TOT (3 * SSTAGE_B)

// Merged projection GEMM: 6 segments (q, qn, k, v, kbk, kbv), all
// fp16-out with per-segment scale. Flat 1D grid of 656 tiles.
//   seg tiles: q 256, qn 256, k 64, v 64, kbk 8, kbv 8
__global__ __launch_bounds__(256, 2) void gemm_proj(
    const __half* __restrict__ X,   // activations [2048, 2048]
    const __half* __restrict__ KIK, const __half* __restrict__ KIV,
    const __half* __restrict__ Wq,  const __half* __restrict__ Wqn,
    const __half* __restrict__ Wk,  const __half* __restrict__ Wv,
    const __half* __restrict__ Wkk, const __half* __restrict__ Wkv,
    __half* __restrict__ Q,  __half* __restrict__ QN,
    __half* __restrict__ Ko, __half* __restrict__ Vo,
    __half* __restrict__ KTK, __half* __restrict__ KTV)
{
    extern __shared__ char sm[];
    int t = blockIdx.x;
    const __half *A, *B;
    __half* C;
    int bx, by, N;
    float esc;
    if (t < 256)      { A = X;   B = Wq;  C = Q;   N = 2048; esc = ESC; int l = t;       bx = l & 15; by = l >> 4; }
    else if (t < 512) { A = X;   B = Wqn; C = QN;  N = 2048; esc = ESC; int l = t - 256; bx = l & 15; by = l >> 4; }
    else if (t < 576) { A = X;   B = Wk;  C = Ko;  N = 512;  esc = 1.f; int l = t - 512; bx = l & 3;  by = l >> 2; }
    else if (t < 640) { A = X;   B = Wv;  C = Vo;  N = 512;  esc = 1.f; int l = t - 576; bx = l & 3;  by = l >> 2; }
    else if (t < 648) { A = KIK; B = Wkk; C = KTK; N = 512;  esc = 1.f; int l = t - 640; bx = l & 3;  by = l >> 2; }
    else              { A = KIV; B = Wkv; C = KTV; N = 512;  esc = 1.f; int l = t - 648; bx = l & 3;  by = l >> 2; }
    const int K = HDIM;

    int tid = threadIdx.x;
    int bm = by * 128;
    int bn = bx * 128;

    int lrow = tid >> 1;
    int lcol = (tid & 1) * 16;
    const __half* gA = A + (size_t)(bm + lrow) * K + lcol;
    const __half* gB = B + (size_t)(bn + lrow) * K + lcol;
    unsigned sBase = smem_u32(sm);
    unsigned sOff = (unsigned)(lrow * TST + lcol) * 2u;

    auto issue = [&](int stage, int k0) {
        unsigned d = sBase + stage * SSTAGE_B + sOff;
        cp16(d,          gA + k0); cp16(d + 16,          gA + k0 + 8);
        cp16(d + TILE_B, gB + k0); cp16(d + TILE_B + 16, gB + k0 + 8);
        asm volatile("cp.async.commit_group;" ::: "memory");
    };

    int wid  = tid >> 5;
    int lane = tid & 31;
    int wm = (wid >> 1) * 32;
    int wn = (wid & 1) * 64;

    float acc[2][8][4];
    #pragma unroll
    for (int i = 0; i < 2; i++)
        #pragma unroll
        for (int j = 0; j < 8; j++)
            #pragma unroll
            for (int c = 0; c < 4; c++) acc[i][j][c] = 0.f;

    int aTerm = (wm + (lane & 15)) * TST + (lane >> 4) * 8;
    int bTerm = (wn + (lane & 15)) * TST + (lane >> 4) * 8;

    const int kIters = K / 32;
    issue(0, 0);
    issue(1, 32);

    for (int it = 0; it < kIters; it++) {
        if (it + 1 < kIters) asm volatile("cp.async.wait_group 1;" ::: "memory");
        else                 asm volatile("cp.async.wait_group 0;" ::: "memory");
        __syncthreads();
        if (it + 2 < kIters) issue((it + 2) % 3, (it + 2) * 32);

        unsigned base = sBase + (unsigned)(it % 3) * SSTAGE_B;
        #pragma unroll
        for (int ks = 0; ks < 2; ks++) {
            int ko = ks * 16;
            unsigned a[2][4];
            #pragma unroll
            for (int mt = 0; mt < 2; mt++) {
                unsigned off = (unsigned)(aTerm + mt * 16 * TST + ko) * 2u;
                ldsm_x4(base + off, a[mt][0], a[mt][1], a[mt][2], a[mt][3]);
            }
            #pragma unroll
            for (int nt2 = 0; nt2 < 4; nt2++) {
                unsigned off = (unsigned)(bTerm + nt2 * 16 * TST + ko) * 2u;
                unsigned r0, r1, r2, r3;
                ldsm_x4(base + TILE_B + off, r0, r1, r2, r3);
                unsigned b0[2] = {r0, r2}, b1[2] = {r1, r3};
                #pragma unroll
                for (int mt = 0; mt < 2; mt++) {
                    mma_f16(acc[mt][2*nt2],   a[mt], b0);
                    mma_f16(acc[mt][2*nt2+1], a[mt], b1);
                }
            }
        }
    }

    int gr = bm + wm + (lane >> 2);
    int gc = bn + wn + (lane & 3) * 2;
    #pragma unroll
    for (int mt = 0; mt < 2; mt++) {
        #pragma unroll
        for (int nt = 0; nt < 8; nt++) {
            int col = gc + nt * 8;
            #pragma unroll
            for (int half = 0; half < 2; half++) {
                int row = gr + mt * 16 + half * 8;
                size_t idx = (size_t)row * N + col;
                float rx = acc[mt][nt][half * 2 + 0] * esc;
                float ry = acc[mt][nt][half * 2 + 1] * esc;
                *(__half2*)(C + idx) = __floats2half2_rn(rx, ry);
            }
        }
    }
}

// gemm_s for o/up/down (round-13 proven). OP: 1 = +D (f32 out), 2 = relu^2.
template<int OP>
__global__ __launch_bounds__(256, 2) void gemm_s(
    const __half* __restrict__ A,  const __half* __restrict__ B,
    float* __restrict__ Cf, const float* __restrict__ D,
    __half* __restrict__ Ch,
    int M, int N, int K)
{
    extern __shared__ char sm[];
    int tid = threadIdx.x;
    int bm = blockIdx.y * 128;
    int bn = blockIdx.x * 128;

    int lrow = tid >> 1;
    int lcol = (tid & 1) * 16;
    const __half* gA = A + (size_t)(bm + lrow) * K + lcol;
    const __half* gB = B + (size_t)(bn + lrow) * K + lcol;
    unsigned sBase = smem_u32(sm);
    unsigned sOff = (unsigned)(lrow * TST + lcol) * 2u;

    auto issue = [&](int stage, int k0) {
        unsigned d = sBase + stage * SSTAGE_B + sOff;
        cp16(d,          gA + k0); cp16(d + 16,          gA + k0 + 8);
        cp16(d + TILE_B, gB + k0); cp16(d + TILE_B + 16, gB + k0 + 8);
        asm volatile("cp.async.commit_group;" ::: "memory");
    };

    int wid  = tid >> 5;
    int lane = tid & 31;
    int wm = (wid >> 1) * 32;
    int wn = (wid & 1) * 64;

    float acc[2][8][4];
    #pragma unroll
    for (int i = 0; i < 2; i++)
        #pragma unroll
        for (int j = 0; j < 8; j++)
            #pragma unroll
            for (int c = 0; c < 4; c++) acc[i][j][c] = 0.f;

    int aTerm = (wm + (lane & 15)) * TST + (lane >> 4) * 8;
    int bTerm = (wn + (lane & 15)) * TST + (lane >> 4) * 8;

    int kIters = K / 32;
    issue(0, 0);
    if (kIters > 1) issue(1, 32);

    for (int it = 0; it < kIters; it++) {
        if (it + 1 < kIters) asm volatile("cp.async.wait_group 1;" ::: "memory");
        else                 asm volatile("cp.async.wait_group 0;" ::: "memory");
        __syncthreads();
        if (it + 2 < kIters) issue((it + 2) % 3, (it + 2) * 32);

        unsigned base = sBase + (unsigned)(it % 3) * SSTAGE_B;
        #pragma unroll
        for (int ks = 0; ks < 2; ks++) {
            int ko = ks * 16;
            unsigned a[2][4];
            #pragma unroll
            for (int mt = 0; mt < 2; mt++) {
                unsigned off = (unsigned)(aTerm + mt * 16 * TST + ko) * 2u;
                ldsm_x4(base + off, a[mt][0], a[mt][1], a[mt][2], a[mt][3]);
            }
            #pragma unroll
            for (int nt2 = 0; nt2 < 4; nt2++) {
                unsigned off = (unsigned)(bTerm + nt2 * 16 * TST + ko) * 2u;
                unsigned r0, r1, r2, r3;
                ldsm_x4(base + TILE_B + off, r0, r1, r2, r3);
                unsigned b0[2] = {r0, r2}, b1[2] = {r1, r3};
                #pragma unroll
                for (int mt = 0; mt < 2; mt++) {
                    mma_f16(acc[mt][2*nt2],   a[mt], b0);
                    mma_f16(acc[mt][2*nt2+1], a[mt], b1);
                }
            }
        }
    }

    int gr = bm + wm + (lane >> 2);
    int gc = bn + wn + (lane & 3) * 2;
    #pragma unroll
    for (int mt = 0; mt < 2; mt++) {
        #pragma unroll
        for (int nt = 0; nt < 8; nt++) {
            int col = gc + nt * 8;
            #pragma unroll
            for (int half = 0; half < 2; half++) {
                int row = gr + mt * 16 + half * 8;
                size_t idx = (size_t)row * N + col;
                float rx = acc[mt][nt][half * 2 + 0];
                float ry = acc[mt][nt][half * 2 + 1];
                if (OP == 1) {
                    float2 d2 = *(const float2*)(D + idx);
                    float2 r; r.x = rx + d2.x; r.y = ry + d2.y;
                    *(float2*)(Cf + idx) = r;
                } else {
                    rx = fmaxf(rx, 0.f); rx *= rx;
                    ry = fmaxf(ry, 0.f); ry *= ry;
                    *(__half2*)(Ch + idx) = __floats2half2_rn(rx, ry);
                }
            }
        }
    }
}

// ---------------------------------------------------------------------------
// Fused RoPE (in-place, fp16 Q/K) + KB assemble (fp16, padded)
// ---------------------------------------------------------------------------
#define ROPE_N (S_LEN * 40 * 32)
#define KBA_N  (NKV * KBPAD * HD)

__global__ __launch_bounds__(256) void rope_kb_kernel(
    __half* __restrict__ Q, __half* __restrict__ K, const int* __restrict__ pos,
    const __half* __restrict__ ktmp, const __half* __restrict__ vtmp,
    const float* __restrict__ sink_k, const float* __restrict__ sink_v,
    __half* __restrict__ kbk, __half* __restrict__ kbv)
{
    int idx = blockIdx.x * blockDim.x + threadIdx.x;
    if (idx < ROPE_N) {
        int d  = idx & 31;
        int hh = (idx >> 5) % 40;
        int s  = idx / (40 * 32);
        float inv = exp2f((float)d * (-13.287712379549449f / 32.0f));
        float ang = (float)pos[s] * inv;
        float sn, cs;
        sincosf(ang, &sn, &cs);
        __half* ptr = (hh < 32) ? (Q + (size_t)s * (NH * HD) + hh * HD)
                                : (K + (size_t)s * (NKV * HD) + (hh - 32) * HD);
        float x1 = __half2float(ptr[d]);
        float x2 = __half2float(ptr[d + 32]);
        ptr[d]      = __float2half_rn(x1 * cs - x2 * sn);
        ptr[d + 32] = __float2half_rn(x2 * cs + x1 * sn);
    } else {
        int j = idx - ROPE_N;
        if (j >= KBA_N) return;
        int d = j % HD;
        int n = (j / HD) % KBPAD;
        int g = j / (HD * KBPAD);
        __half kv = __float2half_rn(0.f), vv = kv;
        if (n == 0) {
            kv = __float2half_rn(sink_k[g * HD + d]);
            vv = __float2half_rn(sink_v[g * HD + d]);
        } else if (n < KBLEN) {
            size_t src = (size_t)(n - 1) * (NKV * HD) + g * HD + d;
            kv = ktmp[src];
            vv = vtmp[src];
        }
        kbk[j] = kv;
        kbv[j] = vv;
    }
}

// ---------------------------------------------------------------------------
// Tensor-core rectangular flash attention (unchanged, round-10 proven)
// ---------------------------------------------------------------------------
#define ATT_ST 72
#define ATT_MATB (64 * ATT_ST * 2)
#define ATT_STGB (2 * ATT_MATB)
#define ATT_QB   (128 * ATT_ST * 2)
#define ATT_SMEM (2 * ATT_STGB + ATT_QB)

__global__ __launch_bounds__(256, 2) void attn_tc_kernel(
    const __half* __restrict__ Qf,  const __half* __restrict__ QNf,
    const __half* __restrict__ Kf,  const __half* __restrict__ Vf,
    const __half* __restrict__ KBKf, const __half* __restrict__ KBVf,
    __half* __restrict__ Of)
{
    extern __shared__ __align__(128) char smraw[];
    unsigned sb = smem_u32(smraw);
    unsigned q_s = sb;
    unsigned stg = sb + ATT_QB;

    int tid = threadIdx.x, wid = tid >> 5, lane = tid & 31;
    int h = blockIdx.y, g = h >> 2;
    int q0 = blockIdx.x * 128;
    int wq = wid * 16;

    float oacc[8][4];
    #pragma unroll
    for (int nt = 0; nt < 8; nt++)
        #pragma unroll
        for (int e = 0; e < 4; e++) oacc[nt][e] = 0.f;
    float lacc[4] = {0.f, 0.f, 0.f, 0.f};
    const unsigned ONES2[2] = {0x3C003C00u, 0x3C003C00u};

    const int aTerm = ((wq + (lane & 15)) * ATT_ST + (lane >> 4) * 8) * 2;
    const int bTerm = (((lane & 15)) * ATT_ST + (lane >> 4) * 8) * 2;

    int r0w = q0 + wq + (lane >> 2);

    for (int phase = 0; phase < 2; phase++) {
        const __half* qsrc = phase ? Qf : QNf;

        __syncthreads();
        #pragma unroll
        for (int u = 0; u < 4; u++) {
            int c = u * 256 + tid;
            int row = c >> 3, cu = c & 7;
            size_t gsrc = (size_t)(q0 + row) * (NH * HD) + h * HD + cu * 8;
            cp16(q_s + (unsigned)(row * ATT_ST * 2 + cu * 16), qsrc + gsrc);
        }
        asm volatile("cp.async.commit_group;" ::: "memory");
        asm volatile("cp.async.wait_group 0;" ::: "memory");
        __syncthreads();

        unsigned qa[4][4];
        #pragma unroll
        for (int ks = 0; ks < 4; ks++)
            ldsm_x4(q_s + aTerm + ks * 32, qa[ks][0], qa[ks][1], qa[ks][2], qa[ks][3]);

        int nb = phase ? ((q0 + 128) >> 6) : (KBPAD >> 6);

        auto kload = [&](int j) {
            unsigned base = stg + (unsigned)(j & 1) * ATT_STGB;
            #pragma unroll
            for (int mt = 0; mt < 2; mt++) {
                const __half* src = phase ? (mt ? Vf : Kf) : (mt ? KBVf : KBKf);
                #pragma unroll
                for (int u = 0; u < 2; u++) {
                    int c = u * 256 + tid;
                    int row = c >> 3, cu = c & 7;
                    size_t gsrc = phase
                        ? ((size_t)(j * 64 + row) * (NKV * HD) + g * HD + cu * 8)
                        : ((size_t)(g * KBPAD + j * 64 + row) * HD + cu * 8);
                    cp16(base + mt * ATT_MATB + (unsigned)(row * ATT_ST * 2 + cu * 16),
                         src + gsrc);
                }
            }
            asm volatile("cp.async.commit_group;" ::: "memory");
        };

        kload(0);

        for (int j = 0; j < nb; j++) {
            if (j + 1 < nb) {
                kload(j + 1);
                asm volatile("cp.async.wait_group 1;" ::: "memory");
            } else {
                asm volatile("cp.async.wait_group 0;" ::: "memory");
            }
            __syncthreads();
            unsigned base = stg + (unsigned)(j & 1) * ATT_STGB;

            int wrow = q0 + wq;
            bool fullMask = phase && (64 * j > wrow + 15);
            if (!fullMask) {
                unsigned sc[8][2];
                #pragma unroll
                for (int nt = 0; nt < 8; nt++) { sc[nt][0] = 0u; sc[nt][1] = 0u; }

                #pragma unroll
                for (int ks = 0; ks < 4; ks++) {
                    #pragma unroll
                    for (int nt2 = 0; nt2 < 4; nt2++) {
                        unsigned off = (unsigned)(bTerm + nt2 * 16 * ATT_ST * 2 + ks * 32);
                        unsigned r0, r1, r2, r3;
                        ldsm_x4(base + off, r0, r1, r2, r3);
                        unsigned bh0[2] = {r0, r2}, bh1[2] = {r1, r3};
                        mma_f16acc(sc[2*nt2],   qa[ks], bh0);
                        mma_f16acc(sc[2*nt2+1], qa[ks], bh1);
                    }
                }

                bool needMask = phase ? (64 * j + 63 > wrow) : (j == nb - 1);
                if (needMask) {
                    int cb = j * 64 + (lane & 3) * 2;
                    #pragma unroll
                    for (int nt = 0; nt < 8; nt++) {
                        int c0 = cb + nt * 8, c1 = c0 + 1;
                        #pragma unroll
                        for (int e = 0; e < 2; e++) {
                            int row = r0w + e * 8;
                            bool m0 = phase ? (c0 > row) : (c0 >= KBLEN);
                            bool m1 = phase ? (c1 > row) : (c1 >= KBLEN);
                            if (m0 | m1) {
                                __half2 add = __floats2half2_rn(m0 ? -1e4f : 0.f,
                                                                m1 ? -1e4f : 0.f);
                                __half2 v = *(__half2*)&sc[nt][e];
                                v = __hadd2(v, add);
                                sc[nt][e] = *(unsigned*)&v;
                            }
                        }
                    }
                }

                unsigned ph[4][4];
                #pragma unroll
                for (int kk = 0; kk < 4; kk++) {
                    ph[kk][0] = ex2_h2(sc[2*kk][0]);
                    ph[kk][1] = ex2_h2(sc[2*kk][1]);
                    ph[kk][2] = ex2_h2(sc[2*kk+1][0]);
                    ph[kk][3] = ex2_h2(sc[2*kk+1][1]);
                }

                #pragma unroll
                for (int kk = 0; kk < 4; kk++)
                    mma_f16(lacc, ph[kk], ONES2);

                #pragma unroll
                for (int kk = 0; kk < 4; kk++) {
                    #pragma unroll
                    for (int nt2 = 0; nt2 < 4; nt2++) {
                        unsigned voff = (unsigned)(((kk * 16 + (lane & 15)) * ATT_ST
                                        + (lane >> 4) * 8 + nt2 * 16) * 2);
                        unsigned t0, t1, t2, t3;
                        ldsm_x4_t(base + ATT_MATB + voff, t0, t1, t2, t3);
                        unsigned vh0[2] = {t0, t1}, vh1[2] = {t2, t3};
                        mma_f16(oacc[2*nt2],   ph[kk], vh0);
                        mma_f16(oacc[2*nt2+1], ph[kk], vh1);
                    }
                }
            }
            __syncthreads();
        }
    }

    float inv0 = 1.0f / lacc[0], inv1 = 1.0f / lacc[2];

    #pragma unroll
    for (int nt = 0; nt < 8; nt++) {
        int col = h * HD + nt * 8 + (lane & 3) * 2;
        {
            __half2 hh = __floats2half2_rn(oacc[nt][0] * inv0, oacc[nt][1] * inv0);
            *(__half2*)(Of + (size_t)r0w * (NH * HD) + col) = hh;
        }
        {
            __half2 hh = __floats2half2_rn(oacc[nt][2] * inv1, oacc[nt][3] * inv1);
            *(__half2*)(Of + (size_t)(r0w + 8) * (NH * HD) + col) = hh;
        }
    }
}

// ---------------------------------------------------------------------------
// kernel_launch
// ---------------------------------------------------------------------------
extern "C" void kernel_launch(void* const* d_in, const int* in_sizes, int n_in,
                              void* d_out, int out_size)
{
    const float* hid     = (const float*)d_in[0];
    const float* kb_keys = (const float*)d_in[1];
    const float* kb_vals = (const float*)d_in[2];
    const float* q_w     = (const float*)d_in[3];
    const float* k_w     = (const float*)d_in[4];
    const float* v_w     = (const float*)d_in[5];
    const float* o_w     = (const float*)d_in[6];
    const float* qnew_w  = (const float*)d_in[7];
    const float* kbk_w   = (const float*)d_in[8];
    const float* kbv_w   = (const float*)d_in[9];
    const float* sink_k  = (const float*)d_in[10];
    const float* sink_v  = (const float*)d_in[11];
    const float* ln1_w   = (const float*)d_in[12];
    const float* ln2_w   = (const float*)d_in[13];
    const float* up_w    = (const float*)d_in[14];
    const float* down_w  = (const float*)d_in[15];
    const int*   pos     = (const int*)d_in[16];
    float* out = (float*)d_out;

    float* H;
    cudaGetSymbolAddress((void**)&H, g_H);

    __half *Wqf,*Wkf,*Wvf,*Wqnf,*Wkkf,*Wkvf,*Wof,*Wupf,*Wdnf;
    __half *X1f,*X2f,*KIKf,*KIVf,*Qf,*QNf,*Kf,*Vf,*KTKf,*KTVf,*KBKf,*KBVf,*ATf,*Uf;
    cudaGetSymbolAddress((void**)&Wqf,  g_Wqf);
    cudaGetSymbolAddress((void**)&Wkf,  g_Wkf);
    cudaGetSymbolAddress((void**)&Wvf,  g_Wvf);
    cudaGetSymbolAddress((void**)&Wqnf, g_Wqnf);
    cudaGetSymbolAddress((void**)&Wkkf, g_Wkkf);
    cudaGetSymbolAddress((void**)&Wkvf, g_Wkvf);
    cudaGetSymbolAddress((void**)&Wof,  g_Wof);
    cudaGetSymbolAddress((void**)&Wupf, g_Wupf);
    cudaGetSymbolAddress((void**)&Wdnf, g_Wdnf);
    cudaGetSymbolAddress((void**)&X1f, g_X1f);  cudaGetSymbolAddress((void**)&X2f, g_X2f);
    cudaGetSymbolAddress((void**)&KIKf,g_KIKf); cudaGetSymbolAddress((void**)&KIVf,g_KIVf);
    cudaGetSymbolAddress((void**)&Qf,  g_Qf);   cudaGetSymbolAddress((void**)&QNf, g_QNf);
    cudaGetSymbolAddress((void**)&Kf,  g_Kf);   cudaGetSymbolAddress((void**)&Vf,  g_Vf);
    cudaGetSymbolAddress((void**)&KTKf,g_KTKf); cudaGetSymbolAddress((void**)&KTVf,g_KTVf);
    cudaGetSymbolAddress((void**)&KBKf,g_KBKf); cudaGetSymbolAddress((void**)&KBVf,g_KBVf);
    cudaGetSymbolAddress((void**)&ATf, g_ATf);  cudaGetSymbolAddress((void**)&Uf,  g_Uf);

    cudaFuncSetAttribute(gemm_proj, cudaFuncAttributeMaxDynamicSharedMemorySize, SSM_TOT);
    cudaFuncSetAttribute(gemm_s<1>, cudaFuncAttributeMaxDynamicSharedMemorySize, SSM_TOT);
    cudaFuncSetAttribute(gemm_s<2>, cudaFuncAttributeMaxDynamicSharedMemorySize, SSM_TOT);
    cudaFuncSetAttribute(attn_tc_kernel, cudaFuncAttributeMaxDynamicSharedMemorySize, ATT_SMEM);

    dim3 blk(256);
    size_t ssm = SSM_TOT;

    // 1: all weight + kb-input converts in one launch
    cvt_all_kernel<<<(CTOT + 1023) / 1024, blk>>>(
        (const float4*)q_w, (const float4*)qnew_w, (const float4*)k_w,
        (const float4*)v_w, (const float4*)kbk_w, (const float4*)kbv_w,
        (const float4*)o_w, (const float4*)up_w, (const float4*)down_w,
        (const float4*)kb_keys, (const float4*)kb_vals,
        (uint2*)Wqf, (uint2*)Wqnf, (uint2*)Wkf, (uint2*)Wvf,
        (uint2*)Wkkf, (uint2*)Wkvf, (uint2*)Wof, (uint2*)Wupf,
        (uint2*)Wdnf, (uint2*)KIKf, (uint2*)KIVf);

    // 2: ln1
    rmsnorm_h_kernel<<<S_LEN, blk>>>(hid, ln1_w, X1f);

    // 3: all six projections in one 656-CTA launch
    gemm_proj<<<656, blk, ssm>>>(X1f, KIKf, KIVf,
                                 Wqf, Wqnf, Wkf, Wvf, Wkkf, Wkvf,
                                 Qf, QNf, Kf, Vf, KTKf, KTVf);

    // 4: fused rope + kb assemble
    rope_kb_kernel<<<(ROPE_N + KBA_N + 255) / 256, blk>>>(
        Qf, Kf, pos, KTKf, KTVf, sink_k, sink_v, KBKf, KBVf);

    // 5: attention
    attn_tc_kernel<<<dim3(S_LEN / 128, NH), blk, ATT_SMEM>>>(
        Qf, QNf, Kf, Vf, KBKf, KBVf, ATf);

    // 6: o-proj + residual -> H (f32)
    gemm_s<1><<<dim3(16, 16), blk, ssm>>>(ATf, Wof, H, hid, nullptr,
                                          S_LEN, HDIM, NH * HD);

    // 7: ln2
    rmsnorm_h_kernel<<<S_LEN, blk>>>(H, ln2_w, X2f);

    // 8: up proj + relu^2
    gemm_s<2><<<dim3(64, 16), blk, ssm>>>(X2f, Wupf, nullptr, nullptr, Uf,
                                          S_LEN, DFF, HDIM);

    // 9: down proj + residual -> out
    gemm_s<1><<<dim3(16, 16), blk, ssm>>>(Uf, Wdnf, out, H, nullptr,
                                          S_LEN, HDIM, DFF);
}